// round 2
// baseline (speedup 1.0000x reference)
#include <cuda_runtime.h>

#define N_NODES 30000
#define IN_C 1024
#define OUT_C 128
#define MAX_DEG 48

// Scratch (allocation-free rule: device globals)
__device__ float g_h[N_NODES * OUT_C];          // 15.36 MB
__device__ int   g_deg[N_NODES];
__device__ int   g_nbr[N_NODES * MAX_DEG];      // 5.76 MB
__device__ int   g_is64;

__global__ void detect_dtype_kernel(const int* __restrict__ ei32) {
    if (threadIdx.x == 0 && blockIdx.x == 0) {
        // int64 layout: (lo,hi) pairs; hi words (odd int32 slots) are all 0
        // for indices in [0, 30000). int32 data has ~0 chance of 32 zeros.
        int is64 = 1;
        #pragma unroll
        for (int s = 1; s < 64; s += 2)
            if (ei32[s] != 0) { is64 = 0; break; }
        g_is64 = is64;
    }
}

__global__ void zero_deg_kernel(int n) {
    int i = blockIdx.x * blockDim.x + threadIdx.x;
    if (i < n) g_deg[i] = 0;
}

// Build dense per-destination neighbor lists (edges + self-loops).
__global__ void build_adj_kernel(const int* __restrict__ ei32, int E, int n) {
    int i = blockIdx.x * blockDim.x + threadIdx.x;
    int total = E + n;
    if (i >= total) return;
    int src, dst;
    if (i < E) {
        if (g_is64) {
            src = ei32[2 * i];            // low word of int64 row[i]
            dst = ei32[2 * (E + i)];      // low word of int64 col[i]
        } else {
            src = ei32[i];
            dst = ei32[E + i];
        }
    } else {
        src = dst = i - E;                // self-loop
    }
    // defensive clamp: never crash on a bad index
    src = min(max(src, 0), n - 1);
    dst = min(max(dst, 0), n - 1);
    int slot = atomicAdd(&g_deg[dst], 1);
    if (slot < MAX_DEG) g_nbr[dst * MAX_DEG + slot] = src;
}

// h = X @ W : [M,1024] x [1024,128] -> [M,128], fp32 tiled SGEMM
// BM=128, BN=128, BK=8, 256 threads, 8x8 per thread.
__global__ __launch_bounds__(256) void gemm_kernel(const float* __restrict__ X,
                                                   const float* __restrict__ W,
                                                   int M) {
    __shared__ float As[8][128];
    __shared__ float Bs[8][128];
    int tid = threadIdx.x;
    int tx = tid & 15;        // 0..15 -> 8 cols each
    int ty = tid >> 4;        // 0..15 -> 8 rows each
    int blockM = blockIdx.x * 128;

    float acc[8][8];
    #pragma unroll
    for (int i = 0; i < 8; i++)
        #pragma unroll
        for (int j = 0; j < 8; j++) acc[i][j] = 0.f;

    int arow = tid >> 1;            // 0..127
    int acol = (tid & 1) * 4;       // 0 or 4
    int brow = tid >> 5;            // 0..7
    int bcol = (tid & 31) * 4;      // 0..124

    int gArow = blockM + arow;
    bool arow_ok = (gArow < M);
    const float* xrow = X + (size_t)gArow * IN_C;

    for (int k0 = 0; k0 < IN_C; k0 += 8) {
        float4 a = arow_ok ? *(const float4*)(xrow + k0 + acol)
                           : make_float4(0.f, 0.f, 0.f, 0.f);
        float4 bv = *(const float4*)(W + (size_t)(k0 + brow) * OUT_C + bcol);
        As[acol + 0][arow] = a.x;
        As[acol + 1][arow] = a.y;
        As[acol + 2][arow] = a.z;
        As[acol + 3][arow] = a.w;
        *(float4*)&Bs[brow][bcol] = bv;
        __syncthreads();
        #pragma unroll
        for (int kk = 0; kk < 8; kk++) {
            float ra[8], rb[8];
            #pragma unroll
            for (int i = 0; i < 8; i++) ra[i] = As[kk][ty * 8 + i];
            #pragma unroll
            for (int j = 0; j < 8; j++) rb[j] = Bs[kk][tx * 8 + j];
            #pragma unroll
            for (int i = 0; i < 8; i++)
                #pragma unroll
                for (int j = 0; j < 8; j++)
                    acc[i][j] = fmaf(ra[i], rb[j], acc[i][j]);
        }
        __syncthreads();
    }

    #pragma unroll
    for (int i = 0; i < 8; i++) {
        int r = blockM + ty * 8 + i;
        if (r < M) {
            float* orow = g_h + (size_t)r * OUT_C + tx * 8;
            *(float4*)(orow)     = make_float4(acc[i][0], acc[i][1], acc[i][2], acc[i][3]);
            *(float4*)(orow + 4) = make_float4(acc[i][4], acc[i][5], acc[i][6], acc[i][7]);
        }
    }
}

// One block per node; 128 threads = one per output channel.
// Each thread gathers d values and partial-selection-sorts to the lower median.
__global__ __launch_bounds__(128) void median_kernel(const float* __restrict__ bias,
                                                     float* __restrict__ out,
                                                     int n) {
    int node = blockIdx.x;
    int c = threadIdx.x;
    __shared__ int snb[MAX_DEG];
    __shared__ int sdeg;

    if (c == 0) sdeg = g_deg[node];
    if (c < MAX_DEG) snb[c] = g_nbr[node * MAX_DEG + c];
    __syncthreads();

    int d = min(sdeg, MAX_DEG);   // self-loops guarantee d >= 1
    float vals[MAX_DEG];
    for (int j = 0; j < d; j++)
        vals[j] = g_h[(size_t)snb[j] * OUT_C + c];

    int k = (d - 1) >> 1;         // lower median index
    for (int t = 0; t <= k; t++) {
        float mn = vals[t];
        int mi = t;
        for (int j = t + 1; j < d; j++) {
            if (vals[j] < mn) { mn = vals[j]; mi = j; }
        }
        vals[mi] = vals[t];
        vals[t] = mn;
    }
    out[(size_t)node * OUT_C + c] = vals[k] + bias[c];
}

extern "C" void kernel_launch(void* const* d_in, const int* in_sizes, int n_in,
                              void* d_out, int out_size) {
    const float* x  = (const float*)d_in[0];
    const int*   ei = (const int*)d_in[1];
    const float* W  = (const float*)d_in[2];
    const float* b  = (const float*)d_in[3];
    float* out = (float*)d_out;

    int n = in_sizes[0] / IN_C;   // 30000
    int E = in_sizes[1] / 2;      // 480000 (element count is dtype-agnostic here)

    detect_dtype_kernel<<<1, 32>>>(ei);
    zero_deg_kernel<<<(n + 255) / 256, 256>>>(n);
    build_adj_kernel<<<(E + n + 255) / 256, 256>>>(ei, E, n);
    gemm_kernel<<<(n + 127) / 128, 256>>>(x, W, n);
    median_kernel<<<n, 128>>>(b, out, n);
}